// round 5
// baseline (speedup 1.0000x reference)
#include <cuda_runtime.h>
#include <cuda_bf16.h>
#include <cstdint>
#include <math.h>

#define NN 50000
#define HH 128
#define EE 600000
#define GG 256
#define OUTD 64
#define NITER 5
#define GAMMA 0.1f
#define EPS 0.1f
#define SLOPE 0.01f

// ---------------- device scratch (static, allocation-free) ----------------
__device__ float g_x[NN * HH];                 // working node features (fp32)
__device__ __nv_bfloat16 g_xhi[NN * HH];       // bf16 split of x, high
__device__ __nv_bfloat16 g_xlo[NN * HH];       // bf16 split of x, low
__device__ float g_nc[NN * 256];               // [neigh(0:128) | conv_lin(128:256)]
__device__ __nv_bfloat16 g_Whi[256 * 128];     // W2 n-major [n][k], bf16 high
__device__ __nv_bfloat16 g_Wlo[256 * 128];     // bf16 low (residual)
__device__ int   g_counts[NN];
__device__ int   g_rowptr[NN + 1];
__device__ int   g_fillptr[NN];
__device__ int   g_srcsorted[EE];
__device__ int   g_gstart[GG + 1];
__device__ float g_pooled[GG * 384];
__device__ float g_h[GG * 192];

__device__ __forceinline__ uint32_t smem_u32(const void* p) {
    uint32_t a;
    asm("{ .reg .u64 t; cvta.to.shared.u64 t, %1; cvt.u32.u64 %0, t; }" : "=r"(a) : "l"(p));
    return a;
}

__device__ __forceinline__ uint32_t bf2pack(float a, float b) {
    __nv_bfloat162 h2 = __floats2bfloat162_rn(a, b);
    return *reinterpret_cast<uint32_t*>(&h2);
}

__device__ __forceinline__ float4 ldcg4(const float* p) {
    float4 v;
    asm volatile("ld.global.cg.v4.f32 {%0,%1,%2,%3}, [%4];"
                 : "=f"(v.x), "=f"(v.y), "=f"(v.z), "=f"(v.w) : "l"(p));
    return v;
}

// ---------------- prep kernels ----------------
__global__ void wprep_kernel(const float* __restrict__ W, const float* __restrict__ lin_w) {
    int n = blockIdx.x;      // 0..255
    int k = threadIdx.x;     // 0..127
    float v;
    if (n < 128) {
        v = lin_w[n * HH + k];
    } else {
        int np = n - 128;
        v = W[np * HH + k] - W[k * HH + np] - (np == k ? GAMMA : 0.0f);
    }
    __nv_bfloat16 hi = __float2bfloat16(v);
    __nv_bfloat16 lo = __float2bfloat16(v - __bfloat162float(hi));
    g_Whi[n * 128 + k] = hi;
    g_Wlo[n * 128 + k] = lo;
}

__global__ void copy_x_kernel(const float* __restrict__ xin) {
    int i = blockIdx.x * blockDim.x + threadIdx.x;
    if (i < NN * HH / 4) {
        float4 f = reinterpret_cast<const float4*>(xin)[i];
        reinterpret_cast<float4*>(g_x)[i] = f;
        uint32_t h0 = bf2pack(f.x, f.y);
        uint32_t h1 = bf2pack(f.z, f.w);
        __nv_bfloat162 hh0 = *reinterpret_cast<__nv_bfloat162*>(&h0);
        __nv_bfloat162 hh1 = *reinterpret_cast<__nv_bfloat162*>(&h1);
        uint32_t l0 = bf2pack(f.x - __bfloat162float(hh0.x), f.y - __bfloat162float(hh0.y));
        uint32_t l1 = bf2pack(f.z - __bfloat162float(hh1.x), f.w - __bfloat162float(hh1.y));
        reinterpret_cast<uint2*>(g_xhi)[i] = make_uint2(h0, h1);
        reinterpret_cast<uint2*>(g_xlo)[i] = make_uint2(l0, l1);
    }
}

__global__ void zero_counts_kernel() {
    int i = blockIdx.x * blockDim.x + threadIdx.x;
    if (i < NN) g_counts[i] = 0;
}

__global__ void hist_kernel(const int* __restrict__ ei) {
    int e = blockIdx.x * blockDim.x + threadIdx.x;
    if (e < EE) {
        int dst = ei[EE + e];
        atomicAdd(&g_counts[dst], 1);
    }
}

// warp-shuffle based scan: 2 barriers per 4096-tile
__global__ void scan_kernel() {
    __shared__ int wsum[32];
    __shared__ int s_run;
    int t = threadIdx.x;
    int lane = t & 31;
    int wid = t >> 5;
    if (t == 0) s_run = 0;
    __syncthreads();
    for (int base = 0; base < NN; base += 4096) {
        int i0 = base + t * 4;
        int v0 = (i0 + 0 < NN) ? g_counts[i0 + 0] : 0;
        int v1 = (i0 + 1 < NN) ? g_counts[i0 + 1] : 0;
        int v2 = (i0 + 2 < NN) ? g_counts[i0 + 2] : 0;
        int v3 = (i0 + 3 < NN) ? g_counts[i0 + 3] : 0;
        int s = v0 + v1 + v2 + v3;
        // warp inclusive scan of s
        int inc = s;
        #pragma unroll
        for (int off = 1; off < 32; off <<= 1) {
            int o = __shfl_up_sync(0xffffffffu, inc, off);
            if (lane >= off) inc += o;
        }
        if (lane == 31) wsum[wid] = inc;
        __syncthreads();
        if (wid == 0) {
            int w = wsum[lane];
            int wi = w;
            #pragma unroll
            for (int off = 1; off < 32; off <<= 1) {
                int o = __shfl_up_sync(0xffffffffu, wi, off);
                if (lane >= off) wi += o;
            }
            wsum[lane] = wi - w;   // exclusive warp offsets
        }
        __syncthreads();
        int run = s_run;
        int acc = run + wsum[wid] + inc - s;   // exclusive prefix for this thread
        if (i0 + 0 < NN) { g_rowptr[i0 + 0] = acc; g_fillptr[i0 + 0] = acc; acc += v0; }
        if (i0 + 1 < NN) { g_rowptr[i0 + 1] = acc; g_fillptr[i0 + 1] = acc; acc += v1; }
        if (i0 + 2 < NN) { g_rowptr[i0 + 2] = acc; g_fillptr[i0 + 2] = acc; acc += v2; }
        if (i0 + 3 < NN) { g_rowptr[i0 + 3] = acc; g_fillptr[i0 + 3] = acc; acc += v3; }
        __syncthreads();
        if (t == 1023) s_run = run + wsum[31] + inc;
        __syncthreads();
    }
    if (t == 0) g_rowptr[NN] = EE;
}

__global__ void fill_kernel(const int* __restrict__ ei) {
    int e = blockIdx.x * blockDim.x + threadIdx.x;
    if (e < EE) {
        int src = ei[e];
        int dst = ei[EE + e];
        int pos = atomicAdd(&g_fillptr[dst], 1);
        g_srcsorted[pos] = src;
    }
}

// ---------------- HMMA GEMM: g_nc = x [NN,128] @ W2^T [128,256] ----------------
#define SROWB 272
#define OFF_AHI 0
#define OFF_ALO 34816                 // 128*272
#define OFF_BHI 69632
#define OFF_BLO 87040                 // 69632 + 64*272
#define SM_TOTAL 104448               // 87040 + 64*272

#define LDM_X4(d, addr) \
    asm volatile("ldmatrix.sync.aligned.m8n8.x4.shared.b16 {%0,%1,%2,%3}, [%4];" \
        : "=r"((d)[0]), "=r"((d)[1]), "=r"((d)[2]), "=r"((d)[3]) : "r"(addr))

#define MMA_BF16(c, a, b) \
    asm volatile("mma.sync.aligned.m16n8k16.row.col.f32.bf16.bf16.f32 " \
        "{%0,%1,%2,%3}, {%4,%5,%6,%7}, {%8,%9}, {%0,%1,%2,%3};" \
        : "+f"((c)[0]), "+f"((c)[1]), "+f"((c)[2]), "+f"((c)[3]) \
        : "r"((a)[0]), "r"((a)[1]), "r"((a)[2]), "r"((a)[3]), "r"((b)[0]), "r"((b)[1]))

__device__ __forceinline__ void cp16(uint32_t dst, const void* src, uint32_t srcsize) {
    asm volatile("cp.async.ca.shared.global [%0], [%1], 16, %2;"
                 :: "r"(dst), "l"(src), "r"(srcsize) : "memory");
}

__global__ __launch_bounds__(256, 2) void gemm_hmma_kernel() {
    extern __shared__ char sm[];
    uint32_t sb = smem_u32(sm);
    int tid = threadIdx.x;
    int warp = tid >> 5;
    int lane = tid & 31;
    int rowbase = blockIdx.x * 128;
    int nbase = blockIdx.y * 64;

    #pragma unroll
    for (int p = 0; p < 8; p++) {
        int j = tid + p * 256;
        int row = j >> 4;
        int c = j & 15;
        int gr = rowbase + row;
        uint32_t ok = (gr < NN) ? 16u : 0u;
        int grc = (gr < NN) ? gr : 0;
        uint32_t doff = (uint32_t)(row * SROWB + c * 16);
        cp16(sb + OFF_AHI + doff, &g_xhi[(size_t)grc * 128 + c * 8], ok);
        cp16(sb + OFF_ALO + doff, &g_xlo[(size_t)grc * 128 + c * 8], ok);
    }
    #pragma unroll
    for (int p = 0; p < 4; p++) {
        int j = tid + p * 256;
        int row = j >> 4;
        int c = j & 15;
        uint32_t doff = (uint32_t)(row * SROWB + c * 16);
        cp16(sb + OFF_BHI + doff, &g_Whi[(size_t)(nbase + row) * 128 + c * 8], 16u);
        cp16(sb + OFF_BLO + doff, &g_Wlo[(size_t)(nbase + row) * 128 + c * 8], 16u);
    }
    asm volatile("cp.async.commit_group;");
    asm volatile("cp.async.wait_group 0;");
    __syncthreads();

    int mrow = (warp & 3) * 32;
    int ncol = (warp >> 2) * 32;
    int g = lane >> 2;
    int tig = lane & 3;

    uint32_t aoffA = (uint32_t)((mrow + (lane & 15)) * SROWB + (lane >> 4) * 16);
    int bm = lane >> 3;
    uint32_t aoffB = (uint32_t)((ncol + ((bm >> 1) << 3) + (lane & 7)) * SROWB + (bm & 1) * 16);

    float acc[2][4][4];
    #pragma unroll
    for (int mt = 0; mt < 2; mt++)
        #pragma unroll
        for (int nt = 0; nt < 4; nt++)
            #pragma unroll
            for (int q = 0; q < 4; q++) acc[mt][nt][q] = 0.f;

    #pragma unroll
    for (int ks = 0; ks < 8; ks++) {
        uint32_t kb = (uint32_t)(ks * 32);
        uint32_t ahi[2][4], alo[2][4], bhi[2][4], blo[2][4];
        #pragma unroll
        for (int mt = 0; mt < 2; mt++) {
            LDM_X4(ahi[mt], sb + OFF_AHI + aoffA + mt * 16 * SROWB + kb);
            LDM_X4(alo[mt], sb + OFF_ALO + aoffA + mt * 16 * SROWB + kb);
        }
        #pragma unroll
        for (int pr = 0; pr < 2; pr++) {
            LDM_X4(bhi[pr], sb + OFF_BHI + aoffB + pr * 16 * SROWB + kb);
            LDM_X4(blo[pr], sb + OFF_BLO + aoffB + pr * 16 * SROWB + kb);
        }
        #pragma unroll
        for (int mt = 0; mt < 2; mt++) {
            #pragma unroll
            for (int nt = 0; nt < 4; nt++) {
                uint32_t bh[2] = {bhi[nt >> 1][(nt & 1) * 2], bhi[nt >> 1][(nt & 1) * 2 + 1]};
                uint32_t bl[2] = {blo[nt >> 1][(nt & 1) * 2], blo[nt >> 1][(nt & 1) * 2 + 1]};
                MMA_BF16(acc[mt][nt], ahi[mt], bh);
                MMA_BF16(acc[mt][nt], alo[mt], bh);
                MMA_BF16(acc[mt][nt], ahi[mt], bl);
            }
        }
    }

    #pragma unroll
    for (int mt = 0; mt < 2; mt++) {
        int r0 = rowbase + mrow + mt * 16 + g;
        int r1 = r0 + 8;
        #pragma unroll
        for (int nt = 0; nt < 4; nt++) {
            int col = nbase + ncol + nt * 8 + 2 * tig;
            if (r0 < NN) {
                *reinterpret_cast<float2*>(&g_nc[(size_t)r0 * 256 + col]) =
                    make_float2(acc[mt][nt][0], acc[mt][nt][1]);
            }
            if (r1 < NN) {
                *reinterpret_cast<float2*>(&g_nc[(size_t)r1 * 256 + col]) =
                    make_float2(acc[mt][nt][2], acc[mt][nt][3]);
            }
        }
    }
}

// ---------------- fused aggregate + conv + tanh + x update (warp per node) ----------------
// 4-wide software-pipelined gather: prefetch next 4 indices while 4 gathers in flight.
__global__ __launch_bounds__(256) void agg_update_kernel(const float* __restrict__ bias) {
    int node = (blockIdx.x * blockDim.x + threadIdx.x) >> 5;
    int lane = threadIdx.x & 31;
    if (node >= NN) return;
    int s = g_rowptr[node];
    int e = g_rowptr[node + 1];

    // issue long-latency independent loads first
    float4 cv = ldcg4(&g_nc[(size_t)node * 256 + 128 + lane * 4]);
    float4 xr = *reinterpret_cast<const float4*>(&g_x[(size_t)node * HH + lane * 4]);
    float4 bv = *reinterpret_cast<const float4*>(&bias[lane * 4]);

    float4 a0 = make_float4(0.f, 0.f, 0.f, 0.f);
    float4 a1 = a0, a2 = a0, a3 = a0;

    int p = s;
    int cnt4 = (e - s) >> 2;
    if (cnt4 > 0) {
        int i0 = g_srcsorted[p + 0];
        int i1 = g_srcsorted[p + 1];
        int i2 = g_srcsorted[p + 2];
        int i3 = g_srcsorted[p + 3];
        p += 4;
        for (int b = 1; b < cnt4; b++) {
            int n0 = g_srcsorted[p + 0];
            int n1 = g_srcsorted[p + 1];
            int n2 = g_srcsorted[p + 2];
            int n3 = g_srcsorted[p + 3];
            float4 v0 = ldcg4(&g_nc[(size_t)i0 * 256 + lane * 4]);
            float4 v1 = ldcg4(&g_nc[(size_t)i1 * 256 + lane * 4]);
            float4 v2 = ldcg4(&g_nc[(size_t)i2 * 256 + lane * 4]);
            float4 v3 = ldcg4(&g_nc[(size_t)i3 * 256 + lane * 4]);
            a0.x += v0.x; a0.y += v0.y; a0.z += v0.z; a0.w += v0.w;
            a1.x += v1.x; a1.y += v1.y; a1.z += v1.z; a1.w += v1.w;
            a2.x += v2.x; a2.y += v2.y; a2.z += v2.z; a2.w += v2.w;
            a3.x += v3.x; a3.y += v3.y; a3.z += v3.z; a3.w += v3.w;
            i0 = n0; i1 = n1; i2 = n2; i3 = n3;
            p += 4;
        }
        float4 v0 = ldcg4(&g_nc[(size_t)i0 * 256 + lane * 4]);
        float4 v1 = ldcg4(&g_nc[(size_t)i1 * 256 + lane * 4]);
        float4 v2 = ldcg4(&g_nc[(size_t)i2 * 256 + lane * 4]);
        float4 v3 = ldcg4(&g_nc[(size_t)i3 * 256 + lane * 4]);
        a0.x += v0.x; a0.y += v0.y; a0.z += v0.z; a0.w += v0.w;
        a1.x += v1.x; a1.y += v1.y; a1.z += v1.z; a1.w += v1.w;
        a2.x += v2.x; a2.y += v2.y; a2.z += v2.z; a2.w += v2.w;
        a3.x += v3.x; a3.y += v3.y; a3.z += v3.z; a3.w += v3.w;
    }
    for (; p < e; p++) {
        int i0 = g_srcsorted[p];
        float4 v0 = ldcg4(&g_nc[(size_t)i0 * 256 + lane * 4]);
        a0.x += v0.x; a0.y += v0.y; a0.z += v0.z; a0.w += v0.w;
    }
    a0.x += a1.x; a0.y += a1.y; a0.z += a1.z; a0.w += a1.w;
    a2.x += a3.x; a2.y += a3.y; a2.z += a3.z; a2.w += a3.w;
    a0.x += a2.x; a0.y += a2.y; a0.z += a2.z; a0.w += a2.w;

    xr.x += EPS * tanhf(cv.x + a0.x + bv.x);
    xr.y += EPS * tanhf(cv.y + a0.y + bv.y);
    xr.z += EPS * tanhf(cv.z + a0.z + bv.z);
    xr.w += EPS * tanhf(cv.w + a0.w + bv.w);
    *reinterpret_cast<float4*>(&g_x[(size_t)node * HH + lane * 4]) = xr;

    uint32_t h0 = bf2pack(xr.x, xr.y);
    uint32_t h1 = bf2pack(xr.z, xr.w);
    __nv_bfloat162 hh0 = *reinterpret_cast<__nv_bfloat162*>(&h0);
    __nv_bfloat162 hh1 = *reinterpret_cast<__nv_bfloat162*>(&h1);
    uint32_t l0 = bf2pack(xr.x - __bfloat162float(hh0.x), xr.y - __bfloat162float(hh0.y));
    uint32_t l1 = bf2pack(xr.z - __bfloat162float(hh1.x), xr.w - __bfloat162float(hh1.y));
    *reinterpret_cast<uint2*>(&g_xhi[(size_t)node * HH + lane * 4]) = make_uint2(h0, h1);
    *reinterpret_cast<uint2*>(&g_xlo[(size_t)node * HH + lane * 4]) = make_uint2(l0, l1);
}

// ---------------- pooling ----------------
__global__ void gstart_kernel(const int* __restrict__ batch) {
    int g = blockIdx.x * blockDim.x + threadIdx.x;
    if (g > GG) return;
    int lo = 0, hi = NN;
    while (lo < hi) {
        int mid = (lo + hi) >> 1;
        if (batch[mid] < g) lo = mid + 1; else hi = mid;
    }
    g_gstart[g] = lo;
}

__global__ void pool_kernel() {
    int g = blockIdx.x;
    int c = threadIdx.x;   // 0..127
    int s = g_gstart[g], e = g_gstart[g + 1];
    float sum = 0.f;
    float mx = -3.402823466e+38f;
    for (int i = s; i < e; i++) {
        float v = g_x[(size_t)i * HH + c];
        sum += v;
        mx = fmaxf(mx, v);
    }
    int cnt = e - s;
    g_pooled[g * 384 + c] = sum;
    g_pooled[g * 384 + 128 + c] = (cnt > 0) ? mx : 0.f;
    g_pooled[g * 384 + 256 + c] = sum / fmaxf((float)cnt, 1.0f);
}

// ---------------- MLP head ----------------
__global__ void mlp1_kernel(const float* __restrict__ l1w, const float* __restrict__ l1b) {
    __shared__ float prow[384];
    int g = blockIdx.x;
    int j = threadIdx.x;   // 0..191
    for (int idx = j; idx < 384; idx += 192) prow[idx] = g_pooled[g * 384 + idx];
    __syncthreads();
    float acc = l1b[j];
    const float* wrow = &l1w[j * 384];
    #pragma unroll 8
    for (int k = 0; k < 384; k++) acc += prow[k] * wrow[k];
    g_h[g * 192 + j] = (acc > 0.f) ? acc : SLOPE * acc;
}

__global__ void mlp2_kernel(const float* __restrict__ l2w, const float* __restrict__ l2b,
                            float* __restrict__ out) {
    __shared__ float hrow[192];
    int g = blockIdx.x;
    int j = threadIdx.x;   // 0..63
    for (int idx = j; idx < 192; idx += 64) hrow[idx] = g_h[g * 192 + idx];
    __syncthreads();
    float acc = l2b[j];
    const float* wrow = &l2w[j * 192];
    #pragma unroll 8
    for (int k = 0; k < 192; k++) acc += hrow[k] * wrow[k];
    out[g * OUTD + j] = (acc > 0.f) ? acc : SLOPE * acc;
}

// ---------------- launch ----------------
extern "C" void kernel_launch(void* const* d_in, const int* in_sizes, int n_in,
                              void* d_out, int out_size) {
    const float* x_in  = (const float*)d_in[0];
    const int*   ei    = (const int*)d_in[1];   // [2,E] int32
    const int*   batch = (const int*)d_in[2];   // [N] int32
    const float* W     = (const float*)d_in[3];
    const float* bias  = (const float*)d_in[4];
    const float* lin_w = (const float*)d_in[5];
    const float* l1w   = (const float*)d_in[6];
    const float* l1b   = (const float*)d_in[7];
    const float* l2w   = (const float*)d_in[8];
    const float* l2b   = (const float*)d_in[9];
    float* out = (float*)d_out;

    cudaFuncSetAttribute(gemm_hmma_kernel, cudaFuncAttributeMaxDynamicSharedMemorySize, SM_TOTAL);

    // prep
    wprep_kernel<<<256, 128>>>(W, lin_w);
    copy_x_kernel<<<(NN * HH / 4 + 255) / 256, 256>>>(x_in);
    zero_counts_kernel<<<(NN + 255) / 256, 256>>>();
    hist_kernel<<<(EE + 255) / 256, 256>>>(ei);
    scan_kernel<<<1, 1024>>>();
    fill_kernel<<<(EE + 255) / 256, 256>>>(ei);

    // 5 propagation iterations
    dim3 ggrid((NN + 127) / 128, 4);
    for (int it = 0; it < NITER; it++) {
        gemm_hmma_kernel<<<ggrid, 256, SM_TOTAL>>>();
        agg_update_kernel<<<(NN * 32 + 255) / 256, 256>>>(bias);
    }

    // pooling + MLP head
    gstart_kernel<<<1, 512>>>(batch);
    pool_kernel<<<GG, HH>>>();
    mlp1_kernel<<<GG, 192>>>(l1w, l1b);
    mlp2_kernel<<<GG, OUTD>>>(l2w, l2b, out);
}

// round 6
// speedup vs baseline: 1.1283x; 1.1283x over previous
#include <cuda_runtime.h>
#include <cuda_bf16.h>
#include <cuda_fp16.h>
#include <cstdint>
#include <math.h>

#define NN 50000
#define HH 128
#define EE 600000
#define GG 256
#define OUTD 64
#define NITER 5
#define GAMMA 0.1f
#define EPS 0.1f
#define SLOPE 0.01f

// ---------------- device scratch (static, allocation-free) ----------------
__device__ float g_x[NN * HH];                 // working node features (fp32)
__device__ __nv_bfloat16 g_xhi[NN * HH];       // bf16 split of x, high
__device__ __nv_bfloat16 g_xlo[NN * HH];       // bf16 split of x, low
__device__ __half g_nh[NN * HH];               // neigh = x@lin_w^T, fp16 (gathered)
__device__ float g_conv[NN * HH];              // conv_lin = x@A^T, fp32
__device__ __nv_bfloat16 g_Whi[256 * 128];     // W2 n-major [n][k], bf16 high
__device__ __nv_bfloat16 g_Wlo[256 * 128];     // bf16 low (residual)
__device__ int   g_counts[NN];
__device__ int   g_rowptr[NN + 1];
__device__ int   g_fillptr[NN];
__device__ int   g_srcsorted[EE];
__device__ int   g_gstart[GG + 1];
__device__ float g_pooled[GG * 384];
__device__ float g_h[GG * 192];

__device__ __forceinline__ uint32_t smem_u32(const void* p) {
    uint32_t a;
    asm("{ .reg .u64 t; cvta.to.shared.u64 t, %1; cvt.u32.u64 %0, t; }" : "=r"(a) : "l"(p));
    return a;
}

__device__ __forceinline__ uint32_t bf2pack(float a, float b) {
    __nv_bfloat162 h2 = __floats2bfloat162_rn(a, b);
    return *reinterpret_cast<uint32_t*>(&h2);
}

// ---------------- prep kernels ----------------
__global__ void wprep_kernel(const float* __restrict__ W, const float* __restrict__ lin_w) {
    int n = blockIdx.x;      // 0..255
    int k = threadIdx.x;     // 0..127
    float v;
    if (n < 128) {
        v = lin_w[n * HH + k];
    } else {
        int np = n - 128;
        v = W[np * HH + k] - W[k * HH + np] - (np == k ? GAMMA : 0.0f);
    }
    __nv_bfloat16 hi = __float2bfloat16(v);
    __nv_bfloat16 lo = __float2bfloat16(v - __bfloat162float(hi));
    g_Whi[n * 128 + k] = hi;
    g_Wlo[n * 128 + k] = lo;
}

__global__ void copy_x_kernel(const float* __restrict__ xin) {
    int i = blockIdx.x * blockDim.x + threadIdx.x;
    if (i < NN * HH / 4) {
        float4 f = reinterpret_cast<const float4*>(xin)[i];
        reinterpret_cast<float4*>(g_x)[i] = f;
        uint32_t h0 = bf2pack(f.x, f.y);
        uint32_t h1 = bf2pack(f.z, f.w);
        __nv_bfloat162 hh0 = *reinterpret_cast<__nv_bfloat162*>(&h0);
        __nv_bfloat162 hh1 = *reinterpret_cast<__nv_bfloat162*>(&h1);
        uint32_t l0 = bf2pack(f.x - __bfloat162float(hh0.x), f.y - __bfloat162float(hh0.y));
        uint32_t l1 = bf2pack(f.z - __bfloat162float(hh1.x), f.w - __bfloat162float(hh1.y));
        reinterpret_cast<uint2*>(g_xhi)[i] = make_uint2(h0, h1);
        reinterpret_cast<uint2*>(g_xlo)[i] = make_uint2(l0, l1);
    }
}

__global__ void zero_counts_kernel() {
    int i = blockIdx.x * blockDim.x + threadIdx.x;
    if (i < NN) g_counts[i] = 0;
}

__global__ void hist_kernel(const int* __restrict__ ei) {
    int e = blockIdx.x * blockDim.x + threadIdx.x;
    if (e < EE) {
        int dst = ei[EE + e];
        atomicAdd(&g_counts[dst], 1);
    }
}

// warp-shuffle based scan
__global__ void scan_kernel() {
    __shared__ int wsum[32];
    __shared__ int s_run;
    int t = threadIdx.x;
    int lane = t & 31;
    int wid = t >> 5;
    if (t == 0) s_run = 0;
    __syncthreads();
    for (int base = 0; base < NN; base += 4096) {
        int i0 = base + t * 4;
        int v0 = (i0 + 0 < NN) ? g_counts[i0 + 0] : 0;
        int v1 = (i0 + 1 < NN) ? g_counts[i0 + 1] : 0;
        int v2 = (i0 + 2 < NN) ? g_counts[i0 + 2] : 0;
        int v3 = (i0 + 3 < NN) ? g_counts[i0 + 3] : 0;
        int s = v0 + v1 + v2 + v3;
        int inc = s;
        #pragma unroll
        for (int off = 1; off < 32; off <<= 1) {
            int o = __shfl_up_sync(0xffffffffu, inc, off);
            if (lane >= off) inc += o;
        }
        if (lane == 31) wsum[wid] = inc;
        __syncthreads();
        if (wid == 0) {
            int w = wsum[lane];
            int wi = w;
            #pragma unroll
            for (int off = 1; off < 32; off <<= 1) {
                int o = __shfl_up_sync(0xffffffffu, wi, off);
                if (lane >= off) wi += o;
            }
            wsum[lane] = wi - w;
        }
        __syncthreads();
        int run = s_run;
        int acc = run + wsum[wid] + inc - s;
        if (i0 + 0 < NN) { g_rowptr[i0 + 0] = acc; g_fillptr[i0 + 0] = acc; acc += v0; }
        if (i0 + 1 < NN) { g_rowptr[i0 + 1] = acc; g_fillptr[i0 + 1] = acc; acc += v1; }
        if (i0 + 2 < NN) { g_rowptr[i0 + 2] = acc; g_fillptr[i0 + 2] = acc; acc += v2; }
        if (i0 + 3 < NN) { g_rowptr[i0 + 3] = acc; g_fillptr[i0 + 3] = acc; acc += v3; }
        __syncthreads();
        if (t == 1023) s_run = run + wsum[31] + inc;
        __syncthreads();
    }
    if (t == 0) g_rowptr[NN] = EE;
}

__global__ void fill_kernel(const int* __restrict__ ei) {
    int e = blockIdx.x * blockDim.x + threadIdx.x;
    if (e < EE) {
        int src = ei[e];
        int dst = ei[EE + e];
        int pos = atomicAdd(&g_fillptr[dst], 1);
        g_srcsorted[pos] = src;
    }
}

// ---------------- HMMA GEMM ----------------
// y=0,1: neigh cols (0..127) -> fp16 g_nh.  y=2,3: conv cols -> fp32 g_conv.
#define SROWB 272
#define OFF_AHI 0
#define OFF_ALO 34816
#define OFF_BHI 69632
#define OFF_BLO 87040
#define SM_TOTAL 104448

#define LDM_X4(d, addr) \
    asm volatile("ldmatrix.sync.aligned.m8n8.x4.shared.b16 {%0,%1,%2,%3}, [%4];" \
        : "=r"((d)[0]), "=r"((d)[1]), "=r"((d)[2]), "=r"((d)[3]) : "r"(addr))

#define MMA_BF16(c, a, b) \
    asm volatile("mma.sync.aligned.m16n8k16.row.col.f32.bf16.bf16.f32 " \
        "{%0,%1,%2,%3}, {%4,%5,%6,%7}, {%8,%9}, {%0,%1,%2,%3};" \
        : "+f"((c)[0]), "+f"((c)[1]), "+f"((c)[2]), "+f"((c)[3]) \
        : "r"((a)[0]), "r"((a)[1]), "r"((a)[2]), "r"((a)[3]), "r"((b)[0]), "r"((b)[1]))

__device__ __forceinline__ void cp16(uint32_t dst, const void* src, uint32_t srcsize) {
    asm volatile("cp.async.ca.shared.global [%0], [%1], 16, %2;"
                 :: "r"(dst), "l"(src), "r"(srcsize) : "memory");
}

__global__ __launch_bounds__(256, 2) void gemm_hmma_kernel() {
    extern __shared__ char sm[];
    uint32_t sb = smem_u32(sm);
    int tid = threadIdx.x;
    int warp = tid >> 5;
    int lane = tid & 31;
    int rowbase = blockIdx.x * 128;
    int nbase = blockIdx.y * 64;

    #pragma unroll
    for (int p = 0; p < 8; p++) {
        int j = tid + p * 256;
        int row = j >> 4;
        int c = j & 15;
        int gr = rowbase + row;
        uint32_t ok = (gr < NN) ? 16u : 0u;
        int grc = (gr < NN) ? gr : 0;
        uint32_t doff = (uint32_t)(row * SROWB + c * 16);
        cp16(sb + OFF_AHI + doff, &g_xhi[(size_t)grc * 128 + c * 8], ok);
        cp16(sb + OFF_ALO + doff, &g_xlo[(size_t)grc * 128 + c * 8], ok);
    }
    #pragma unroll
    for (int p = 0; p < 4; p++) {
        int j = tid + p * 256;
        int row = j >> 4;
        int c = j & 15;
        uint32_t doff = (uint32_t)(row * SROWB + c * 16);
        cp16(sb + OFF_BHI + doff, &g_Whi[(size_t)(nbase + row) * 128 + c * 8], 16u);
        cp16(sb + OFF_BLO + doff, &g_Wlo[(size_t)(nbase + row) * 128 + c * 8], 16u);
    }
    asm volatile("cp.async.commit_group;");
    asm volatile("cp.async.wait_group 0;");
    __syncthreads();

    int mrow = (warp & 3) * 32;
    int ncol = (warp >> 2) * 32;
    int g = lane >> 2;
    int tig = lane & 3;

    uint32_t aoffA = (uint32_t)((mrow + (lane & 15)) * SROWB + (lane >> 4) * 16);
    int bm = lane >> 3;
    uint32_t aoffB = (uint32_t)((ncol + ((bm >> 1) << 3) + (lane & 7)) * SROWB + (bm & 1) * 16);

    float acc[2][4][4];
    #pragma unroll
    for (int mt = 0; mt < 2; mt++)
        #pragma unroll
        for (int nt = 0; nt < 4; nt++)
            #pragma unroll
            for (int q = 0; q < 4; q++) acc[mt][nt][q] = 0.f;

    #pragma unroll
    for (int ks = 0; ks < 8; ks++) {
        uint32_t kb = (uint32_t)(ks * 32);
        uint32_t ahi[2][4], alo[2][4], bhi[2][4], blo[2][4];
        #pragma unroll
        for (int mt = 0; mt < 2; mt++) {
            LDM_X4(ahi[mt], sb + OFF_AHI + aoffA + mt * 16 * SROWB + kb);
            LDM_X4(alo[mt], sb + OFF_ALO + aoffA + mt * 16 * SROWB + kb);
        }
        #pragma unroll
        for (int pr = 0; pr < 2; pr++) {
            LDM_X4(bhi[pr], sb + OFF_BHI + aoffB + pr * 16 * SROWB + kb);
            LDM_X4(blo[pr], sb + OFF_BLO + aoffB + pr * 16 * SROWB + kb);
        }
        #pragma unroll
        for (int mt = 0; mt < 2; mt++) {
            #pragma unroll
            for (int nt = 0; nt < 4; nt++) {
                uint32_t bh[2] = {bhi[nt >> 1][(nt & 1) * 2], bhi[nt >> 1][(nt & 1) * 2 + 1]};
                uint32_t bl[2] = {blo[nt >> 1][(nt & 1) * 2], blo[nt >> 1][(nt & 1) * 2 + 1]};
                MMA_BF16(acc[mt][nt], ahi[mt], bh);
                MMA_BF16(acc[mt][nt], alo[mt], bh);
                MMA_BF16(acc[mt][nt], ahi[mt], bl);
            }
        }
    }

    // ---- epilogue: neigh (y<2) -> fp16 g_nh; conv (y>=2) -> fp32 g_conv ----
    bool is_neigh = (nbase < 128);
    int cb = is_neigh ? nbase : (nbase - 128);
    #pragma unroll
    for (int mt = 0; mt < 2; mt++) {
        int r0 = rowbase + mrow + mt * 16 + g;
        int r1 = r0 + 8;
        #pragma unroll
        for (int nt = 0; nt < 4; nt++) {
            int col = cb + ncol + nt * 8 + 2 * tig;
            if (is_neigh) {
                __half2 p0 = __floats2half2_rn(acc[mt][nt][0], acc[mt][nt][1]);
                __half2 p1 = __floats2half2_rn(acc[mt][nt][2], acc[mt][nt][3]);
                if (r0 < NN) *reinterpret_cast<__half2*>(&g_nh[(size_t)r0 * 128 + col]) = p0;
                if (r1 < NN) *reinterpret_cast<__half2*>(&g_nh[(size_t)r1 * 128 + col]) = p1;
            } else {
                if (r0 < NN) *reinterpret_cast<float2*>(&g_conv[(size_t)r0 * 128 + col]) =
                    make_float2(acc[mt][nt][0], acc[mt][nt][1]);
                if (r1 < NN) *reinterpret_cast<float2*>(&g_conv[(size_t)r1 * 128 + col]) =
                    make_float2(acc[mt][nt][2], acc[mt][nt][3]);
            }
        }
    }
}

// ---------------- fused aggregate + conv + tanh + x update (warp per node) ----------------
// Plain loads (no volatile asm) so ptxas can batch/pipeline. fp16 gather, fp32 accum.
__global__ __launch_bounds__(256) void agg_update_kernel(const float* __restrict__ bias) {
    int node = (blockIdx.x * blockDim.x + threadIdx.x) >> 5;
    int lane = threadIdx.x & 31;
    if (node >= NN) return;
    int s = g_rowptr[node];
    int e = g_rowptr[node + 1];

    float4 cv = *reinterpret_cast<const float4*>(&g_conv[(size_t)node * 128 + lane * 4]);
    float4 xr = *reinterpret_cast<const float4*>(&g_x[(size_t)node * HH + lane * 4]);
    float4 bv = *reinterpret_cast<const float4*>(&bias[lane * 4]);

    float4 a0 = make_float4(0.f, 0.f, 0.f, 0.f);
    float4 a1 = a0, a2 = a0, a3 = a0;

    int p = s;
    for (; p + 3 < e; p += 4) {
        int i0 = g_srcsorted[p + 0];
        int i1 = g_srcsorted[p + 1];
        int i2 = g_srcsorted[p + 2];
        int i3 = g_srcsorted[p + 3];
        uint2 u0 = *reinterpret_cast<const uint2*>(&g_nh[(size_t)i0 * 128 + lane * 4]);
        uint2 u1 = *reinterpret_cast<const uint2*>(&g_nh[(size_t)i1 * 128 + lane * 4]);
        uint2 u2 = *reinterpret_cast<const uint2*>(&g_nh[(size_t)i2 * 128 + lane * 4]);
        uint2 u3 = *reinterpret_cast<const uint2*>(&g_nh[(size_t)i3 * 128 + lane * 4]);
        float2 f;
        f = __half22float2(*reinterpret_cast<__half2*>(&u0.x)); a0.x += f.x; a0.y += f.y;
        f = __half22float2(*reinterpret_cast<__half2*>(&u0.y)); a0.z += f.x; a0.w += f.y;
        f = __half22float2(*reinterpret_cast<__half2*>(&u1.x)); a1.x += f.x; a1.y += f.y;
        f = __half22float2(*reinterpret_cast<__half2*>(&u1.y)); a1.z += f.x; a1.w += f.y;
        f = __half22float2(*reinterpret_cast<__half2*>(&u2.x)); a2.x += f.x; a2.y += f.y;
        f = __half22float2(*reinterpret_cast<__half2*>(&u2.y)); a2.z += f.x; a2.w += f.y;
        f = __half22float2(*reinterpret_cast<__half2*>(&u3.x)); a3.x += f.x; a3.y += f.y;
        f = __half22float2(*reinterpret_cast<__half2*>(&u3.y)); a3.z += f.x; a3.w += f.y;
    }
    for (; p < e; p++) {
        int i0 = g_srcsorted[p];
        uint2 u0 = *reinterpret_cast<const uint2*>(&g_nh[(size_t)i0 * 128 + lane * 4]);
        float2 f;
        f = __half22float2(*reinterpret_cast<__half2*>(&u0.x)); a0.x += f.x; a0.y += f.y;
        f = __half22float2(*reinterpret_cast<__half2*>(&u0.y)); a0.z += f.x; a0.w += f.y;
    }
    a0.x += a1.x; a0.y += a1.y; a0.z += a1.z; a0.w += a1.w;
    a2.x += a3.x; a2.y += a3.y; a2.z += a3.z; a2.w += a3.w;
    a0.x += a2.x; a0.y += a2.y; a0.z += a2.z; a0.w += a2.w;

    xr.x += EPS * tanhf(cv.x + a0.x + bv.x);
    xr.y += EPS * tanhf(cv.y + a0.y + bv.y);
    xr.z += EPS * tanhf(cv.z + a0.z + bv.z);
    xr.w += EPS * tanhf(cv.w + a0.w + bv.w);
    *reinterpret_cast<float4*>(&g_x[(size_t)node * HH + lane * 4]) = xr;

    uint32_t h0 = bf2pack(xr.x, xr.y);
    uint32_t h1 = bf2pack(xr.z, xr.w);
    __nv_bfloat162 hh0 = *reinterpret_cast<__nv_bfloat162*>(&h0);
    __nv_bfloat162 hh1 = *reinterpret_cast<__nv_bfloat162*>(&h1);
    uint32_t l0 = bf2pack(xr.x - __bfloat162float(hh0.x), xr.y - __bfloat162float(hh0.y));
    uint32_t l1 = bf2pack(xr.z - __bfloat162float(hh1.x), xr.w - __bfloat162float(hh1.y));
    *reinterpret_cast<uint2*>(&g_xhi[(size_t)node * HH + lane * 4]) = make_uint2(h0, h1);
    *reinterpret_cast<uint2*>(&g_xlo[(size_t)node * HH + lane * 4]) = make_uint2(l0, l1);
}

// ---------------- pooling ----------------
__global__ void gstart_kernel(const int* __restrict__ batch) {
    int g = blockIdx.x * blockDim.x + threadIdx.x;
    if (g > GG) return;
    int lo = 0, hi = NN;
    while (lo < hi) {
        int mid = (lo + hi) >> 1;
        if (batch[mid] < g) lo = mid + 1; else hi = mid;
    }
    g_gstart[g] = lo;
}

__global__ void pool_kernel() {
    int g = blockIdx.x;
    int c = threadIdx.x;   // 0..127
    int s = g_gstart[g], e = g_gstart[g + 1];
    float sum = 0.f;
    float mx = -3.402823466e+38f;
    for (int i = s; i < e; i++) {
        float v = g_x[(size_t)i * HH + c];
        sum += v;
        mx = fmaxf(mx, v);
    }
    int cnt = e - s;
    g_pooled[g * 384 + c] = sum;
    g_pooled[g * 384 + 128 + c] = (cnt > 0) ? mx : 0.f;
    g_pooled[g * 384 + 256 + c] = sum / fmaxf((float)cnt, 1.0f);
}

// ---------------- MLP head ----------------
__global__ void mlp1_kernel(const float* __restrict__ l1w, const float* __restrict__ l1b) {
    __shared__ float prow[384];
    int g = blockIdx.x;
    int j = threadIdx.x;   // 0..191
    for (int idx = j; idx < 384; idx += 192) prow[idx] = g_pooled[g * 384 + idx];
    __syncthreads();
    float acc = l1b[j];
    const float* wrow = &l1w[j * 384];
    #pragma unroll 8
    for (int k = 0; k < 384; k++) acc += prow[k] * wrow[k];
    g_h[g * 192 + j] = (acc > 0.f) ? acc : SLOPE * acc;
}

__global__ void mlp2_kernel(const float* __restrict__ l2w, const float* __restrict__ l2b,
                            float* __restrict__ out) {
    __shared__ float hrow[192];
    int g = blockIdx.x;
    int j = threadIdx.x;   // 0..63
    for (int idx = j; idx < 192; idx += 64) hrow[idx] = g_h[g * 192 + idx];
    __syncthreads();
    float acc = l2b[j];
    const float* wrow = &l2w[j * 192];
    #pragma unroll 8
    for (int k = 0; k < 192; k++) acc += hrow[k] * wrow[k];
    out[g * OUTD + j] = (acc > 0.f) ? acc : SLOPE * acc;
}

// ---------------- launch ----------------
extern "C" void kernel_launch(void* const* d_in, const int* in_sizes, int n_in,
                              void* d_out, int out_size) {
    const float* x_in  = (const float*)d_in[0];
    const int*   ei    = (const int*)d_in[1];
    const int*   batch = (const int*)d_in[2];
    const float* W     = (const float*)d_in[3];
    const float* bias  = (const float*)d_in[4];
    const float* lin_w = (const float*)d_in[5];
    const float* l1w   = (const float*)d_in[6];
    const float* l1b   = (const float*)d_in[7];
    const float* l2w   = (const float*)d_in[8];
    const float* l2b   = (const float*)d_in[9];
    float* out = (float*)d_out;

    cudaFuncSetAttribute(gemm_hmma_kernel, cudaFuncAttributeMaxDynamicSharedMemorySize, SM_TOTAL);

    // prep
    wprep_kernel<<<256, 128>>>(W, lin_w);
    copy_x_kernel<<<(NN * HH / 4 + 255) / 256, 256>>>(x_in);
    zero_counts_kernel<<<(NN + 255) / 256, 256>>>();
    hist_kernel<<<(EE + 255) / 256, 256>>>(ei);
    scan_kernel<<<1, 1024>>>();
    fill_kernel<<<(EE + 255) / 256, 256>>>(ei);

    // 5 propagation iterations
    dim3 ggrid((NN + 127) / 128, 4);
    for (int it = 0; it < NITER; it++) {
        gemm_hmma_kernel<<<ggrid, 256, SM_TOTAL>>>();
        agg_update_kernel<<<(NN * 32 + 255) / 256, 256>>>(bias);
    }

    // pooling + MLP head
    gstart_kernel<<<1, 512>>>(batch);
    pool_kernel<<<GG, HH>>>();
    mlp1_kernel<<<GG, 192>>>(l1w, l1b);
    mlp2_kernel<<<GG, OUTD>>>(l2w, l2b, out);
}